// round 11
// baseline (speedup 1.0000x reference)
#include <cuda_runtime.h>
#include <cuda_bf16.h>
#include <cstdint>

#define N_NODES 100000
#define N_EDGES 1600000
#define HH      128
#define N_SUB   10000
#define N_GRAPH 64

// Scratch (device globals; allocation-free)
__device__ float g_aggs[N_NODES];                 // scalar agg for layer 1
__device__ float g_buf0[(size_t)N_NODES * HH];
__device__ float g_buf1[(size_t)N_NODES * HH];
__device__ float g_buf2[(size_t)N_NODES * HH];
__device__ int   g_ng[N_NODES];                   // node -> graph
__device__ int2  g_edge[N_EDGES];                 // packed (src, dst)

// ---------------------------------------------------------------------------
// Kernel 0: pack edge_index [2,E] int32 -> interleaved int2
// ---------------------------------------------------------------------------
__global__ void edge_prep_kernel(const int* __restrict__ ei)
{
    int e = blockIdx.x * blockDim.x + threadIdx.x;
    if (e >= N_EDGES) return;
    int2 p;
    p.x = ei[e];                  // src
    p.y = ei[N_EDGES + e];        // dst
    g_edge[e] = p;
}

// ---------------------------------------------------------------------------
// Kernel 1: zero aggs + output, precompute node->graph
// ---------------------------------------------------------------------------
__global__ void init_kernel(const int* __restrict__ n2s,
                            const int* __restrict__ s2g,
                            float* __restrict__ out)
{
    int i = blockIdx.x * blockDim.x + threadIdx.x;
    if (i < N_NODES) {
        g_aggs[i] = 0.0f;
        g_ng[i] = s2g[n2s[i]];
    }
    if (i < N_GRAPH * HH) out[i] = 0.0f;
}

// ---------------------------------------------------------------------------
// Kernel 2: scalar edge aggregation for layer 1 (x is [N,1])
// ---------------------------------------------------------------------------
__global__ void edge_scalar_kernel(const float* __restrict__ x)
{
    int e = blockIdx.x * blockDim.x + threadIdx.x;
    if (e >= N_EDGES) return;
    int2 p = g_edge[e];
    atomicAdd(&g_aggs[p.y], __ldg(&x[p.x]));
}

// ---------------------------------------------------------------------------
// Kernel 3: layer-1 first MLP (broadcast):  hv = relu((x+agg) * W1 + b1)
// ---------------------------------------------------------------------------
__global__ void layer1_elem_kernel(const float* __restrict__ x,
                                   const float* __restrict__ W1,
                                   const float* __restrict__ b1,
                                   float* __restrict__ out)
{
    int idx = blockIdx.x * blockDim.x + threadIdx.x;
    if (idx >= N_NODES * HH) return;
    int n = idx >> 7;
    int c = idx & 127;
    float s = x[n] + g_aggs[n];
    float v = fmaf(s, __ldg(&W1[c]), __ldg(&b1[c]));
    out[idx] = fmaxf(v, 0.0f);
}

// ---------------------------------------------------------------------------
// Kernel 4: GEMM + bias + relu:  out[n,c] = relu(sum_k in[n,k]*W[k,c] + b[c])
//   block = 128 threads (one per output column), 8-node tiles, grid-stride.
//   smem: W (64KB) + transposed A-tile [k][8] (4KB)
// ---------------------------------------------------------------------------
__global__ void gemm_relu_kernel(const float* __restrict__ in,
                                 const float* __restrict__ W,
                                 const float* __restrict__ bias,
                                 float* __restrict__ out,
                                 int nrows)
{
    extern __shared__ float sm[];
    float* Wsm = sm;                // HH*HH
    float* Asm = sm + HH * HH;      // 8*HH, layout [k][j]
    int c = threadIdx.x;

    // cooperative W load (vectorized)
    const float4* Wsrc = (const float4*)W;
    float4* Wdst = (float4*)Wsm;
    #pragma unroll
    for (int i = c; i < HH * HH / 4; i += HH) Wdst[i] = Wsrc[i];
    float bc = bias[c];
    __syncthreads();

    for (int tile = blockIdx.x * 8; tile < nrows; tile += gridDim.x * 8) {
        // load 8 rows transposed: Asm[k*8+j] = in[(tile+j)*HH + k], this thread does k=c
        #pragma unroll
        for (int j = 0; j < 8; j++)
            Asm[c * 8 + j] = in[(size_t)(tile + j) * HH + c];
        __syncthreads();

        float a0 = 0.f, a1 = 0.f, a2 = 0.f, a3 = 0.f;
        float a4 = 0.f, a5 = 0.f, a6 = 0.f, a7 = 0.f;
        const float4* Av = (const float4*)Asm;
        #pragma unroll
        for (int k = 0; k < HH; k++) {
            float w = Wsm[k * HH + c];
            float4 p = Av[k * 2];
            float4 q = Av[k * 2 + 1];
            a0 = fmaf(p.x, w, a0); a1 = fmaf(p.y, w, a1);
            a2 = fmaf(p.z, w, a2); a3 = fmaf(p.w, w, a3);
            a4 = fmaf(q.x, w, a4); a5 = fmaf(q.y, w, a5);
            a6 = fmaf(q.z, w, a6); a7 = fmaf(q.w, w, a7);
        }
        float acc[8] = {a0, a1, a2, a3, a4, a5, a6, a7};
        #pragma unroll
        for (int j = 0; j < 8; j++)
            out[(size_t)(tile + j) * HH + c] = fmaxf(acc[j] + bc, 0.0f);
        __syncthreads();
    }
}

// ---------------------------------------------------------------------------
// Kernel 5: vector copy (agg buffer := h, the (1+eps)*x self term)
// ---------------------------------------------------------------------------
__global__ void copy_kernel(const float4* __restrict__ src, float4* __restrict__ dst, int n4)
{
    int i = blockIdx.x * blockDim.x + threadIdx.x;
    if (i < n4) dst[i] = src[i];
}

// ---------------------------------------------------------------------------
// Kernel 6: 128-wide edge scatter-add: hout[dst] += hin[src].  Warp per edge.
// ---------------------------------------------------------------------------
__global__ void edge_add_kernel(const float* __restrict__ hin,
                                float* __restrict__ hout)
{
    int warp = (blockIdx.x * blockDim.x + threadIdx.x) >> 5;
    int lane = threadIdx.x & 31;
    if (warp >= N_EDGES) return;
    int2 p = g_edge[warp];
    float4 v = *(const float4*)(hin + (size_t)p.x * HH + lane * 4);
    atomicAdd((float4*)(hout + (size_t)p.y * HH + lane * 4), v);
}

// ---------------------------------------------------------------------------
// Kernel 7: pooling.  node->graph is nondecreasing (both maps sorted), so
// run-length accumulate per contiguous node range, flush on change.
// Correct even if unsorted (atomicAdd on every flush).
// ---------------------------------------------------------------------------
__global__ void pool_kernel(const float* __restrict__ h,
                            float* __restrict__ out,
                            int nodes_per_block)
{
    int c = threadIdx.x;
    int n0 = blockIdx.x * nodes_per_block;
    if (n0 >= N_NODES) return;
    int n1 = n0 + nodes_per_block;
    if (n1 > N_NODES) n1 = N_NODES;

    int gcur = g_ng[n0];
    float sum = 0.0f;
    for (int n = n0; n < n1; n++) {
        int g = g_ng[n];
        if (g != gcur) {
            atomicAdd(&out[gcur * HH + c], sum);
            sum = 0.0f;
            gcur = g;
        }
        sum += h[(size_t)n * HH + c];
    }
    atomicAdd(&out[gcur * HH + c], sum);
}

// ---------------------------------------------------------------------------
// Host
// ---------------------------------------------------------------------------
extern "C" void kernel_launch(void* const* d_in, const int* in_sizes, int n_in,
                              void* d_out, int out_size)
{
    // NOTE: JAX default config has x64 disabled, so the "int64" index tensors
    // are materialized as int32 on the wire.
    const float* x   = (const float*)d_in[0];
    const int*   ei  = (const int*)d_in[1];
    const int*   n2s = (const int*)d_in[2];
    const int*   s2g = (const int*)d_in[3];
    const float* c1W1 = (const float*)d_in[4];
    const float* c1b1 = (const float*)d_in[5];
    const float* c1W2 = (const float*)d_in[6];
    const float* c1b2 = (const float*)d_in[7];
    const float* cW1  = (const float*)d_in[8];   // [2,H,H]
    const float* cb1  = (const float*)d_in[9];   // [2,H]
    const float* cW2  = (const float*)d_in[10];
    const float* cb2  = (const float*)d_in[11];
    float* out = (float*)d_out;

    float *buf0, *buf1, *buf2;
    cudaGetSymbolAddress((void**)&buf0, g_buf0);
    cudaGetSymbolAddress((void**)&buf1, g_buf1);
    cudaGetSymbolAddress((void**)&buf2, g_buf2);

    const int gemm_smem = (HH * HH + 8 * HH) * (int)sizeof(float);  // 69632
    cudaFuncSetAttribute(gemm_relu_kernel,
                         cudaFuncAttributeMaxDynamicSharedMemorySize, gemm_smem);

    const int GEMM_GRID = 444;  // 148 SMs * 3 blocks/SM (smem-limited)
    const int NH = N_NODES * HH;

    // 0) edge packing + init
    edge_prep_kernel<<<(N_EDGES + 255) / 256, 256>>>(ei);
    init_kernel<<<(N_NODES + 255) / 256, 256>>>(n2s, s2g, out);

    // 1) layer 1: scalar aggregation -> broadcast MLP1 -> GEMM MLP2
    edge_scalar_kernel<<<(N_EDGES + 255) / 256, 256>>>(x);
    layer1_elem_kernel<<<(NH + 255) / 256, 256>>>(x, c1W1, c1b1, buf2);
    gemm_relu_kernel<<<GEMM_GRID, HH, gemm_smem>>>(buf2, c1W2, c1b2, buf0, N_NODES);
    // h after layer 1 in buf0

    // 2) layers 2 and 3 (convs index 0, 1)
    for (int L = 0; L < 2; L++) {
        const float* W1 = cW1 + (size_t)L * HH * HH;
        const float* b1 = cb1 + (size_t)L * HH;
        const float* W2 = cW2 + (size_t)L * HH * HH;
        const float* b2 = cb2 + (size_t)L * HH;

        // agg := h  (self term, eps=0)
        copy_kernel<<<(NH / 4 + 255) / 256, 256>>>((const float4*)buf0, (float4*)buf1, NH / 4);
        // agg += scatter(h over edges)
        edge_add_kernel<<<(N_EDGES * 32 + 255) / 256, 256>>>(buf0, buf1);
        // MLP
        gemm_relu_kernel<<<GEMM_GRID, HH, gemm_smem>>>(buf1, W1, b1, buf2, N_NODES);
        gemm_relu_kernel<<<GEMM_GRID, HH, gemm_smem>>>(buf2, W2, b2, buf0, N_NODES);
    }

    // 3) hierarchical pooling (node->subgraph->graph == node->graph, both sorted)
    const int NODES_PER_BLOCK = 128;
    int pool_blocks = (N_NODES + NODES_PER_BLOCK - 1) / NODES_PER_BLOCK;
    pool_kernel<<<pool_blocks, HH>>>(buf0, out, NODES_PER_BLOCK);
}

// round 16
// speedup vs baseline: 2.5974x; 2.5974x over previous
#include <cuda_runtime.h>
#include <cuda_bf16.h>
#include <cstdint>

#define N_NODES 100000
#define N_PAD   100096            // 782 * 128, padded row count for GEMM tiles
#define N_EDGES 1600000
#define HH      128
#define N_SUB   10000
#define N_GRAPH 64
#define N_TILES (N_PAD / 128)     // 782
#define SCAN_BLOCKS 391           // ceil(100000/256)

// Scratch (device globals; allocation-free). Zero-initialized at load.
__device__ float g_aggs[N_NODES];
__device__ float g_buf0[(size_t)N_PAD * HH];
__device__ float g_buf1[(size_t)N_PAD * HH];
__device__ float g_buf2[(size_t)N_PAD * HH];
__device__ int   g_ng[N_NODES];                // node -> graph
__device__ int   g_deg[N_NODES];
__device__ int   g_cnt[N_NODES];
__device__ int   g_rowptr[N_NODES + 1];
__device__ int   g_csr[N_EDGES];
__device__ int   g_partials[512];

// ---------------------------------------------------------------------------
// init: zero deg/cnt + output, precompute node->graph
// ---------------------------------------------------------------------------
__global__ void init_kernel(const int* __restrict__ n2s,
                            const int* __restrict__ s2g,
                            float* __restrict__ out)
{
    int i = blockIdx.x * blockDim.x + threadIdx.x;
    if (i < N_NODES) {
        g_deg[i] = 0;
        g_cnt[i] = 0;
        g_ng[i] = s2g[n2s[i]];
    }
    if (i < N_GRAPH * HH) out[i] = 0.0f;
}

// ---------------------------------------------------------------------------
// CSR build: degree count -> 2-level exclusive scan -> fill
// ---------------------------------------------------------------------------
__global__ void deg_kernel(const int* __restrict__ ei)
{
    int e = blockIdx.x * blockDim.x + threadIdx.x;
    if (e >= N_EDGES) return;
    atomicAdd(&g_deg[ei[N_EDGES + e]], 1);
}

__global__ void scanA_kernel()
{
    __shared__ int sm[256];
    int tid = threadIdx.x;
    int i = blockIdx.x * 256 + tid;
    int v = (i < N_NODES) ? g_deg[i] : 0;
    sm[tid] = v;
    __syncthreads();
    #pragma unroll
    for (int off = 1; off < 256; off <<= 1) {
        int u = (tid >= off) ? sm[tid - off] : 0;
        int t = sm[tid];
        __syncthreads();
        sm[tid] = t + u;
        __syncthreads();
    }
    if (i < N_NODES) g_rowptr[i] = sm[tid] - v;     // exclusive within block
    if (tid == 255) g_partials[blockIdx.x] = sm[255];
}

__global__ void scanB_kernel()
{
    __shared__ int sm[512];
    int tid = threadIdx.x;
    int v = (tid < SCAN_BLOCKS) ? g_partials[tid] : 0;
    sm[tid] = v;
    __syncthreads();
    #pragma unroll
    for (int off = 1; off < 512; off <<= 1) {
        int u = (tid >= off) ? sm[tid - off] : 0;
        int t = sm[tid];
        __syncthreads();
        sm[tid] = t + u;
        __syncthreads();
    }
    if (tid < SCAN_BLOCKS) g_partials[tid] = sm[tid] - v;  // exclusive
}

__global__ void scanC_kernel()
{
    int i = blockIdx.x * blockDim.x + threadIdx.x;
    if (i < N_NODES) g_rowptr[i] += g_partials[i >> 8];
    if (i == 0) g_rowptr[N_NODES] = N_EDGES;
}

__global__ void fill_kernel(const int* __restrict__ ei)
{
    int e = blockIdx.x * blockDim.x + threadIdx.x;
    if (e >= N_EDGES) return;
    int src = ei[e];
    int dst = ei[N_EDGES + e];
    int pos = g_rowptr[dst] + atomicAdd(&g_cnt[dst], 1);
    g_csr[pos] = src;
}

// ---------------------------------------------------------------------------
// layer-1 scalar aggregation via CSR:  aggs[n] = x[n] + sum x[src]
// ---------------------------------------------------------------------------
__global__ void gather_scalar_kernel(const float* __restrict__ x)
{
    int n = blockIdx.x * blockDim.x + threadIdx.x;
    if (n >= N_NODES) return;
    int beg = g_rowptr[n], end = g_rowptr[n + 1];
    float s = x[n];
    for (int i = beg; i < end; i++) s += __ldg(&x[g_csr[i]]);
    g_aggs[n] = s;
}

// ---------------------------------------------------------------------------
// layer-1 first MLP (broadcast):  buf = relu(aggs[n] * W1 + b1)
// ---------------------------------------------------------------------------
__global__ void layer1_elem_kernel(const float* __restrict__ W1,
                                   const float* __restrict__ b1,
                                   float* __restrict__ out)
{
    int idx = blockIdx.x * blockDim.x + threadIdx.x;
    if (idx >= N_NODES * HH) return;
    int n = idx >> 7;
    int c = idx & 127;
    float v = fmaf(g_aggs[n], __ldg(&W1[c]), __ldg(&b1[c]));
    out[idx] = fmaxf(v, 0.0f);
}

// ---------------------------------------------------------------------------
// 128-wide CSR gather:  outb[n] = h[n] + sum_{s in N(n)} h[s]    (warp/node)
// Neighbor indices fetched by lane 0 as two SCALAR loads (int2 would be
// misaligned for odd row starts), broadcast via shfl.
// ---------------------------------------------------------------------------
__global__ void gather_vec_kernel(const float* __restrict__ h,
                                  float* __restrict__ outb)
{
    int node = (blockIdx.x * blockDim.x + threadIdx.x) >> 5;
    int lane = threadIdx.x & 31;
    if (node >= N_NODES) return;
    int beg = g_rowptr[node], end = g_rowptr[node + 1];
    const float4* hp = (const float4*)h;
    float4 acc = hp[(size_t)node * 32 + lane];   // self term (eps=0)
    int i = beg;
    for (; i + 1 < end; i += 2) {
        int s0 = 0, s1 = 0;
        if (lane == 0) { s0 = g_csr[i]; s1 = g_csr[i + 1]; }
        s0 = __shfl_sync(0xffffffffu, s0, 0);
        s1 = __shfl_sync(0xffffffffu, s1, 0);
        float4 v0 = hp[(size_t)s0 * 32 + lane];
        float4 v1 = hp[(size_t)s1 * 32 + lane];
        acc.x += v0.x + v1.x; acc.y += v0.y + v1.y;
        acc.z += v0.z + v1.z; acc.w += v0.w + v1.w;
    }
    if (i < end) {
        int s = (lane == 0) ? g_csr[i] : 0;
        s = __shfl_sync(0xffffffffu, s, 0);
        float4 v = hp[(size_t)s * 32 + lane];
        acc.x += v.x; acc.y += v.y; acc.z += v.z; acc.w += v.w;
    }
    ((float4*)outb)[(size_t)node * 32 + lane] = acc;
}

// ---------------------------------------------------------------------------
// Tensor-core GEMM + bias + relu (tf32 mma.sync.m16n8k8)
//   out[r,c] = relu(sum_k in[r,k] * W[k,c] + b[c]);  in/out padded to N_PAD rows.
//   Block = 128 thr (4 warps); block tile = 128 rows; warp = 32 rows x 128 cols.
//   W pre-packed in smem as per-lane B fragments -> one conflict-free LDS.64/mma-pair.
// ---------------------------------------------------------------------------
__device__ __forceinline__ uint32_t f2tf32(float f)
{
    uint32_t u;
    asm("cvt.rna.tf32.f32 %0, %1;" : "=r"(u) : "f"(f));
    return u;
}

__device__ __forceinline__ void mma_tf32(float c[4], const uint32_t a[4],
                                         uint32_t b0, uint32_t b1)
{
    asm volatile(
        "mma.sync.aligned.m16n8k8.row.col.f32.tf32.tf32.f32 "
        "{%0,%1,%2,%3}, {%4,%5,%6,%7}, {%8,%9}, {%0,%1,%2,%3};"
        : "+f"(c[0]), "+f"(c[1]), "+f"(c[2]), "+f"(c[3])
        : "r"(a[0]), "r"(a[1]), "r"(a[2]), "r"(a[3]), "r"(b0), "r"(b1));
}

#define GEMM_SMEM (16 * 16 * 32 * 8 + 512)   // Bfrag[16][16][32] uint2 + bias

__global__ void __launch_bounds__(128, 2)
gemm_tc_kernel(const float* __restrict__ in, const float* __restrict__ W,
               const float* __restrict__ bias, float* __restrict__ out,
               int ntiles)
{
    extern __shared__ uint2 Bf[];                 // [ks][nb][lane]
    float* bsm = (float*)(Bf + 16 * 16 * 32);
    int tid = threadIdx.x;
    int wid = tid >> 5, lane = tid & 31;
    int g = lane >> 2, t = lane & 3;

    // Pack W into mma B fragments (col-major frag of W[k0+t][nb*8+g], k0+t+4)
    for (int i = tid; i < 16 * 16 * 32; i += 128) {
        int l = i & 31, nb = (i >> 5) & 15, ks = i >> 9;
        int tt = l & 3, gg = l >> 2;
        int n = nb * 8 + gg, k0 = ks * 8;
        uint2 u;
        u.x = f2tf32(W[(k0 + tt) * HH + n]);
        u.y = f2tf32(W[(k0 + tt + 4) * HH + n]);
        Bf[i] = u;
    }
    if (tid < HH) bsm[tid] = bias[tid];
    __syncthreads();

    for (int tile = blockIdx.x; tile < ntiles; tile += gridDim.x) {
        int r0 = tile * 128 + wid * 32;            // this warp: rows r0..r0+31
        float c[2][16][4];
        #pragma unroll
        for (int m = 0; m < 2; m++)
            #pragma unroll
            for (int nb = 0; nb < 16; nb++)
                #pragma unroll
                for (int q = 0; q < 4; q++) c[m][nb][q] = 0.0f;

        #pragma unroll 2
        for (int ks = 0; ks < 16; ks++) {
            int k0 = ks * 8;
            uint32_t a[2][4];
            #pragma unroll
            for (int m = 0; m < 2; m++) {
                const float* base = in + (size_t)(r0 + m * 16 + g) * HH + k0 + t;
                a[m][0] = f2tf32(base[0]);
                a[m][1] = f2tf32(base[8 * HH]);
                a[m][2] = f2tf32(base[4]);
                a[m][3] = f2tf32(base[8 * HH + 4]);
            }
            const uint2* bp = Bf + ks * 512 + lane;
            #pragma unroll
            for (int nb = 0; nb < 16; nb++) {
                uint2 b = bp[nb * 32];
                mma_tf32(c[0][nb], a[0], b.x, b.y);
                mma_tf32(c[1][nb], a[1], b.x, b.y);
            }
        }

        // epilogue: c0->(row g, col 2t), c1->(g,2t+1), c2->(g+8,2t), c3->(g+8,2t+1)
        #pragma unroll
        for (int m = 0; m < 2; m++) {
            int row = r0 + m * 16 + g;
            #pragma unroll
            for (int nb = 0; nb < 16; nb++) {
                int col = nb * 8 + t * 2;
                float b0 = bsm[col], b1 = bsm[col + 1];
                float2 v;
                v.x = fmaxf(c[m][nb][0] + b0, 0.0f);
                v.y = fmaxf(c[m][nb][1] + b1, 0.0f);
                *(float2*)(out + (size_t)row * HH + col) = v;
                v.x = fmaxf(c[m][nb][2] + b0, 0.0f);
                v.y = fmaxf(c[m][nb][3] + b1, 0.0f);
                *(float2*)(out + (size_t)(row + 8) * HH + col) = v;
            }
        }
    }
}

// ---------------------------------------------------------------------------
// pooling: node->graph nondecreasing; run-length accumulate, flush on change
// ---------------------------------------------------------------------------
__global__ void pool_kernel(const float* __restrict__ h,
                            float* __restrict__ out,
                            int nodes_per_block)
{
    int c = threadIdx.x;
    int n0 = blockIdx.x * nodes_per_block;
    if (n0 >= N_NODES) return;
    int n1 = n0 + nodes_per_block;
    if (n1 > N_NODES) n1 = N_NODES;

    int gcur = g_ng[n0];
    float sum = 0.0f;
    for (int n = n0; n < n1; n++) {
        int g = g_ng[n];
        if (g != gcur) {
            atomicAdd(&out[gcur * HH + c], sum);
            sum = 0.0f;
            gcur = g;
        }
        sum += h[(size_t)n * HH + c];
    }
    atomicAdd(&out[gcur * HH + c], sum);
}

// ---------------------------------------------------------------------------
// Host
// ---------------------------------------------------------------------------
extern "C" void kernel_launch(void* const* d_in, const int* in_sizes, int n_in,
                              void* d_out, int out_size)
{
    // JAX x64 is disabled -> index tensors materialize as int32.
    const float* x   = (const float*)d_in[0];
    const int*   ei  = (const int*)d_in[1];
    const int*   n2s = (const int*)d_in[2];
    const int*   s2g = (const int*)d_in[3];
    const float* c1W1 = (const float*)d_in[4];
    const float* c1b1 = (const float*)d_in[5];
    const float* c1W2 = (const float*)d_in[6];
    const float* c1b2 = (const float*)d_in[7];
    const float* cW1  = (const float*)d_in[8];
    const float* cb1  = (const float*)d_in[9];
    const float* cW2  = (const float*)d_in[10];
    const float* cb2  = (const float*)d_in[11];
    float* out = (float*)d_out;

    float *buf0, *buf1, *buf2;
    cudaGetSymbolAddress((void**)&buf0, g_buf0);
    cudaGetSymbolAddress((void**)&buf1, g_buf1);
    cudaGetSymbolAddress((void**)&buf2, g_buf2);

    cudaFuncSetAttribute(gemm_tc_kernel,
                         cudaFuncAttributeMaxDynamicSharedMemorySize, GEMM_SMEM);

    const int GEMM_GRID = 296;   // 148 SMs * 2 blocks (reg/smem limited)
    const int NH = N_NODES * HH;

    // 0) init + CSR build
    init_kernel<<<SCAN_BLOCKS, 256>>>(n2s, s2g, out);
    deg_kernel<<<(N_EDGES + 255) / 256, 256>>>(ei);
    scanA_kernel<<<SCAN_BLOCKS, 256>>>();
    scanB_kernel<<<1, 512>>>();
    scanC_kernel<<<SCAN_BLOCKS, 256>>>();
    fill_kernel<<<(N_EDGES + 255) / 256, 256>>>(ei);

    // 1) layer 1: scalar CSR gather -> broadcast MLP1 -> tensor-core MLP2
    gather_scalar_kernel<<<SCAN_BLOCKS, 256>>>(x);
    layer1_elem_kernel<<<(NH + 255) / 256, 256>>>(c1W1, c1b1, buf2);
    gemm_tc_kernel<<<GEMM_GRID, 128, GEMM_SMEM>>>(buf2, c1W2, c1b2, buf0, N_TILES);

    // 2) layers 2 and 3
    for (int L = 0; L < 2; L++) {
        const float* W1 = cW1 + (size_t)L * HH * HH;
        const float* b1 = cb1 + (size_t)L * HH;
        const float* W2 = cW2 + (size_t)L * HH * HH;
        const float* b2 = cb2 + (size_t)L * HH;

        gather_vec_kernel<<<(N_NODES * 32 + 255) / 256, 256>>>(buf0, buf1);
        gemm_tc_kernel<<<GEMM_GRID, 128, GEMM_SMEM>>>(buf1, W1, b1, buf2, N_TILES);
        gemm_tc_kernel<<<GEMM_GRID, 128, GEMM_SMEM>>>(buf2, W2, b2, buf0, N_TILES);
    }

    // 3) hierarchical pooling
    const int NODES_PER_BLOCK = 128;
    int pool_blocks = (N_NODES + NODES_PER_BLOCK - 1) / NODES_PER_BLOCK;
    pool_kernel<<<pool_blocks, HH>>>(buf0, out, NODES_PER_BLOCK);
}